// round 4
// baseline (speedup 1.0000x reference)
#include <cuda_runtime.h>

#define N_MAX 50000
#define E_MAX 800000

// Scratch (allocation-free rule: __device__ globals)
__device__ float g_agg[N_MAX * 64];
__device__ float g_cnt[N_MAX];
__device__ int g_row[E_MAX];
__device__ int g_col[E_MAX];
__device__ int g_is32;  // 1 if edge_index is int32, 0 if int64

__device__ __forceinline__ float lrelu(float v) { return v > 0.f ? v : 0.01f * v; }

// Computes 4 rows x (lane-owned 4 output units) of out = lrelu(in @ W + b).
// Ain/Bout are per-warp SMEM buffers with row stride 128.
template <int KIN>
__device__ __forceinline__ void layer4(const float* __restrict__ W,
                                       const float* __restrict__ bias,
                                       const float* __restrict__ Ain,
                                       float* __restrict__ Bout, int lane) {
    float4 bb = *(const float4*)(bias + 4 * lane);
    float acc[4][4];
#pragma unroll
    for (int e = 0; e < 4; e++) {
        acc[e][0] = bb.x; acc[e][1] = bb.y; acc[e][2] = bb.z; acc[e][3] = bb.w;
    }
    for (int k = 0; k < KIN; k += 4) {
        float4 a[4];
#pragma unroll
        for (int e = 0; e < 4; e++) a[e] = *(const float4*)(Ain + e * 128 + k);
#pragma unroll
        for (int kk = 0; kk < 4; kk++) {
            float4 w = *(const float4*)(W + (k + kk) * 128 + 4 * lane);
#pragma unroll
            for (int e = 0; e < 4; e++) {
                float av = ((const float*)&a[e])[kk];
                acc[e][0] = fmaf(av, w.x, acc[e][0]);
                acc[e][1] = fmaf(av, w.y, acc[e][1]);
                acc[e][2] = fmaf(av, w.z, acc[e][2]);
                acc[e][3] = fmaf(av, w.w, acc[e][3]);
            }
        }
    }
#pragma unroll
    for (int e = 0; e < 4; e++) {
        float4 o;
        o.x = lrelu(acc[e][0]); o.y = lrelu(acc[e][1]);
        o.z = lrelu(acc[e][2]); o.w = lrelu(acc[e][3]);
        *(float4*)(Bout + e * 128 + 4 * lane) = o;
    }
}

// Final 64-wide layer: lane owns 2 output units, result kept in registers.
template <int KIN>
__device__ __forceinline__ void layer2(const float* __restrict__ W,
                                       const float* __restrict__ bias,
                                       const float* __restrict__ Ain,
                                       float out[4][2], int lane) {
    float2 bb = *(const float2*)(bias + 2 * lane);
    float acc[4][2];
#pragma unroll
    for (int e = 0; e < 4; e++) { acc[e][0] = bb.x; acc[e][1] = bb.y; }
    for (int k = 0; k < KIN; k += 4) {
        float4 a[4];
#pragma unroll
        for (int e = 0; e < 4; e++) a[e] = *(const float4*)(Ain + e * 128 + k);
#pragma unroll
        for (int kk = 0; kk < 4; kk++) {
            float2 w = *(const float2*)(W + (k + kk) * 64 + 2 * lane);
#pragma unroll
            for (int e = 0; e < 4; e++) {
                float av = ((const float*)&a[e])[kk];
                acc[e][0] = fmaf(av, w.x, acc[e][0]);
                acc[e][1] = fmaf(av, w.y, acc[e][1]);
            }
        }
    }
#pragma unroll
    for (int e = 0; e < 4; e++) { out[e][0] = lrelu(acc[e][0]); out[e][1] = lrelu(acc[e][1]); }
}

// LayerNorm over 64 features distributed 2-per-lane across the warp.
__device__ __forceinline__ void ln64(float& v0, float& v1, float2 g2, float2 t2) {
    float s = v0 + v1;
#pragma unroll
    for (int off = 16; off; off >>= 1) s += __shfl_xor_sync(0xffffffffu, s, off);
    float mean = s * (1.0f / 64.0f);
    float d0 = v0 - mean, d1 = v1 - mean;
    float q = d0 * d0 + d1 * d1;
#pragma unroll
    for (int off = 16; off; off >>= 1) q += __shfl_xor_sync(0xffffffffu, q, off);
    float rstd = rsqrtf(q * (1.0f / 64.0f) + 1e-5f);
    v0 = d0 * rstd * g2.x + t2.x;
    v1 = d1 * rstd * g2.y + t2.y;
}

__global__ void zero_kernel(int N) {
    int i = blockIdx.x * blockDim.x + threadIdx.x;
    int stride = gridDim.x * blockDim.x;
    if (i == 0) g_is32 = 0;
    int n4 = N * 16;  // N*64 floats / 4
    float4 z = make_float4(0.f, 0.f, 0.f, 0.f);
    for (int j = i; j < n4; j += stride) ((float4*)g_agg)[j] = z;
    for (int j = i; j < N; j += stride) g_cnt[j] = 0.f;
}

// Dtype probe: interpret first E words of edge_index as int64 (always within
// the buffer for both int32 and int64 data). Genuine int64 data -> all values
// in [0, N). int32 data -> words are packed (lo,hi) index pairs; any nonzero
// hi word pushes the value >= 2^32 -> flag.
__global__ void detect_kernel(const long long* __restrict__ ei64, int E, int N) {
    int i = blockIdx.x * blockDim.x + threadIdx.x;
    int stride = gridDim.x * blockDim.x;
    int bad = 0;
    for (int j = i; j < E; j += stride) {
        long long v = ei64[j];
        if (v < 0 || v >= (long long)N) bad = 1;
    }
    if (__ballot_sync(0xffffffffu, bad) && (threadIdx.x & 31) == 0)
        atomicOr(&g_is32, 1);
}

// Expand edge_index into clamped int32 row/col scratch arrays.
__global__ void convert_kernel(const void* __restrict__ eiraw, int E, int N) {
    int i = blockIdx.x * blockDim.x + threadIdx.x;
    int stride = gridDim.x * blockDim.x;
    int is32 = g_is32;
    if (is32) {
        const int* p = (const int*)eiraw;
        for (int j = i; j < E; j += stride) {
            int r = p[j], c = p[E + j];
            g_row[j] = min(max(r, 0), N - 1);
            g_col[j] = min(max(c, 0), N - 1);
        }
    } else {
        const long long* p = (const long long*)eiraw;
        for (int j = i; j < E; j += stride) {
            int r = (int)p[j], c = (int)p[E + j];
            g_row[j] = min(max(r, 0), N - 1);
            g_col[j] = min(max(c, 0), N - 1);
        }
    }
}

// ---------------------------------------------------------------------------
// Edge kernel: h = LN(MLP1(concat(x[row], edge_attr))); atomic scatter to agg.
// ---------------------------------------------------------------------------
__global__ __launch_bounds__(512, 1) void edge_kernel(
    const float* __restrict__ x,
    const float* __restrict__ ea,
    const float* __restrict__ w0g, const float* __restrict__ b0g,
    const float* __restrict__ w1g, const float* __restrict__ b1g,
    const float* __restrict__ w2g, const float* __restrict__ b2g,
    const float* __restrict__ gg, const float* __restrict__ btg, int E) {
    extern __shared__ float sm[];
    float* w0 = sm;                   // 96*128
    float* w1 = w0 + 96 * 128;        // 128*128
    float* w2 = w1 + 128 * 128;       // 128*64
    float* b0 = w2 + 128 * 64;        // 128
    float* b1 = b0 + 128;             // 128
    float* b2 = b1 + 128;             // 64
    float* gl = b2 + 64;              // 64
    float* bl = gl + 64;              // 64
    float* acts = bl + 64;            // 16 warps * 1024

    int tid = threadIdx.x, T = blockDim.x;
    for (int i = tid * 4; i < 96 * 128; i += T * 4) *(float4*)(w0 + i) = *(const float4*)(w0g + i);
    for (int i = tid * 4; i < 128 * 128; i += T * 4) *(float4*)(w1 + i) = *(const float4*)(w1g + i);
    for (int i = tid * 4; i < 128 * 64; i += T * 4) *(float4*)(w2 + i) = *(const float4*)(w2g + i);
    if (tid < 128) { b0[tid] = b0g[tid]; b1[tid] = b1g[tid]; }
    if (tid < 64) { b2[tid] = b2g[tid]; gl[tid] = gg[tid]; bl[tid] = btg[tid]; }
    __syncthreads();

    int warp = tid >> 5, lane = tid & 31;
    float* A = acts + warp * 1024;
    float* B = A + 512;
    float2 g2 = *(const float2*)(gl + 2 * lane);
    float2 t2 = *(const float2*)(bl + 2 * lane);

    int nwarp = gridDim.x * (T >> 5);
    int gw = blockIdx.x * (T >> 5) + warp;
    int ngroups = (E + 3) >> 2;
    for (int gi = gw; gi < ngroups; gi += nwarp) {
        int e0 = gi << 2;
        // Gather: 4 edges x 96 features (x[row] 64 ++ edge_attr 32)
        for (int i = lane; i < 4 * 96; i += 32) {
            int el = i / 96, f = i - el * 96;
            int e = e0 + el;
            float v = 0.f;
            if (e < E) {
                if (f < 64) {
                    int r = g_row[e];
                    v = __ldg(x + r * 64 + f);
                } else {
                    v = ea[(long long)e * 32 + (f - 64)];
                }
            }
            A[el * 128 + f] = v;
        }
        __syncwarp();
        layer4<96>(w0, b0, A, B, lane);
        __syncwarp();
        layer4<128>(w1, b1, B, A, lane);
        __syncwarp();
        float o[4][2];
        layer2<128>(w2, b2, A, o, lane);
#pragma unroll
        for (int el = 0; el < 4; el++) {
            ln64(o[el][0], o[el][1], g2, t2);
            int e = e0 + el;
            if (e < E) {
                int c = g_col[e];
                atomicAdd(g_agg + c * 64 + 2 * lane, o[el][0]);
                atomicAdd(g_agg + c * 64 + 2 * lane + 1, o[el][1]);
                if (lane == 0) atomicAdd(g_cnt + c, 1.0f);
            }
        }
        __syncwarp();
    }
}

// ---------------------------------------------------------------------------
// Node kernel: out = LN(MLP2(concat(x, agg/max(cnt,1))))
// ---------------------------------------------------------------------------
__global__ __launch_bounds__(512, 1) void node_kernel(
    const float* __restrict__ x,
    const float* __restrict__ w0g, const float* __restrict__ b0g,
    const float* __restrict__ w1g, const float* __restrict__ b1g,
    const float* __restrict__ w2g, const float* __restrict__ b2g,
    const float* __restrict__ gg, const float* __restrict__ btg,
    float* __restrict__ out, int N) {
    extern __shared__ float sm[];
    float* w0 = sm;                  // 128*128
    float* w1 = w0 + 128 * 128;      // 128*128
    float* w2 = w1 + 128 * 128;      // 128*64
    float* b0 = w2 + 128 * 64;
    float* b1 = b0 + 128;
    float* b2 = b1 + 128;
    float* gl = b2 + 64;
    float* bl = gl + 64;
    float* acts = bl + 64;

    int tid = threadIdx.x, T = blockDim.x;
    for (int i = tid * 4; i < 128 * 128; i += T * 4) *(float4*)(w0 + i) = *(const float4*)(w0g + i);
    for (int i = tid * 4; i < 128 * 128; i += T * 4) *(float4*)(w1 + i) = *(const float4*)(w1g + i);
    for (int i = tid * 4; i < 128 * 64; i += T * 4) *(float4*)(w2 + i) = *(const float4*)(w2g + i);
    if (tid < 128) { b0[tid] = b0g[tid]; b1[tid] = b1g[tid]; }
    if (tid < 64) { b2[tid] = b2g[tid]; gl[tid] = gg[tid]; bl[tid] = btg[tid]; }
    __syncthreads();

    int warp = tid >> 5, lane = tid & 31;
    float* A = acts + warp * 1024;
    float* B = A + 512;
    float2 g2 = *(const float2*)(gl + 2 * lane);
    float2 t2 = *(const float2*)(bl + 2 * lane);

    int nwarp = gridDim.x * (T >> 5);
    int gw = blockIdx.x * (T >> 5) + warp;
    int ngroups = (N + 3) >> 2;
    for (int gi = gw; gi < ngroups; gi += nwarp) {
        int n0 = gi << 2;
        // Gather: 4 nodes x 128 features (x 64 ++ agg/max(cnt,1) 64)
        for (int i = lane; i < 4 * 128; i += 32) {
            int el = i >> 7, f = i & 127;
            int n = n0 + el;
            float v = 0.f;
            if (n < N) {
                if (f < 64) {
                    v = x[n * 64 + f];
                } else {
                    v = g_agg[n * 64 + (f - 64)] / fmaxf(g_cnt[n], 1.0f);
                }
            }
            A[el * 128 + f] = v;
        }
        __syncwarp();
        layer4<128>(w0, b0, A, B, lane);
        __syncwarp();
        layer4<128>(w1, b1, B, A, lane);
        __syncwarp();
        float o[4][2];
        layer2<128>(w2, b2, A, o, lane);
#pragma unroll
        for (int el = 0; el < 4; el++) {
            ln64(o[el][0], o[el][1], g2, t2);
            int n = n0 + el;
            if (n < N) {
                *(float2*)(out + (long long)n * 64 + 2 * lane) = make_float2(o[el][0], o[el][1]);
            }
        }
        __syncwarp();
    }
}

extern "C" void kernel_launch(void* const* d_in, const int* in_sizes, int n_in,
                              void* d_out, int out_size) {
    const float* x = (const float*)d_in[0];
    const void* ei = (const void*)d_in[1];
    const float* ea = (const float*)d_in[2];
    // d_in[3] = u (unused), d_in[4] = batch (unused)
    const float* m1w0 = (const float*)d_in[5];
    const float* m1b0 = (const float*)d_in[6];
    const float* m1w1 = (const float*)d_in[7];
    const float* m1b1 = (const float*)d_in[8];
    const float* m1w2 = (const float*)d_in[9];
    const float* m1b2 = (const float*)d_in[10];
    const float* ln1g = (const float*)d_in[11];
    const float* ln1b = (const float*)d_in[12];
    const float* m2w0 = (const float*)d_in[13];
    const float* m2b0 = (const float*)d_in[14];
    const float* m2w1 = (const float*)d_in[15];
    const float* m2b1 = (const float*)d_in[16];
    const float* m2w2 = (const float*)d_in[17];
    const float* m2b2 = (const float*)d_in[18];
    const float* ln2g = (const float*)d_in[19];
    const float* ln2b = (const float*)d_in[20];

    int N = in_sizes[0] / 64;
    int E = in_sizes[1] / 2;
    if (N > N_MAX) N = N_MAX;
    if (E > E_MAX) E = E_MAX;
    float* out = (float*)d_out;

    int dev = 0;
    cudaGetDevice(&dev);
    int nsm = 148;
    cudaDeviceGetAttribute(&nsm, cudaDevAttrMultiProcessorCount, dev);

    zero_kernel<<<256, 256>>>(N);
    detect_kernel<<<512, 256>>>((const long long*)ei, E, N);
    convert_kernel<<<512, 256>>>(ei, E, N);

    size_t smE = (size_t)(96 * 128 + 128 * 128 + 128 * 64 + 448 + 16 * 1024) * 4;
    size_t smN = (size_t)(128 * 128 + 128 * 128 + 128 * 64 + 448 + 16 * 1024) * 4;
    cudaFuncSetAttribute(edge_kernel, cudaFuncAttributeMaxDynamicSharedMemorySize, (int)smE);
    cudaFuncSetAttribute(node_kernel, cudaFuncAttributeMaxDynamicSharedMemorySize, (int)smN);

    edge_kernel<<<nsm, 512, smE>>>(x, ea, m1w0, m1b0, m1w1, m1b1, m1w2, m1b2,
                                   ln1g, ln1b, E);
    node_kernel<<<nsm, 512, smN>>>(x, m2w0, m2b0, m2w1, m2b1, m2w2, m2b2,
                                   ln2g, ln2b, out, N);
}

// round 7
// speedup vs baseline: 1.3726x; 1.3726x over previous
#include <cuda_runtime.h>
#include <mma.h>

using namespace nvcuda;

#define N_MAX 50000
#define E_MAX 800000

// Scratch (allocation-free rule: __device__ globals)
__device__ float g_agg[N_MAX * 64];
__device__ float g_cnt[N_MAX];
__device__ int g_row[E_MAX];
__device__ int g_col[E_MAX];
__device__ int g_is32;

// ---------------------------------------------------------------------------
__device__ __forceinline__ float lrelu(float v) { return v > 0.f ? v : 0.01f * v; }

// tf32 round-to-nearest (rna); result is fp32 with low mantissa cleared
__device__ __forceinline__ float to_tf32(float v) {
    unsigned o;
    asm("cvt.rna.tf32.f32 %0, %1;" : "=r"(o) : "f"(v));
    return __uint_as_float(o);
}

__device__ __forceinline__ void red_add_v4(float* p, float a, float b, float c, float d) {
    asm volatile("red.global.add.v4.f32 [%0], {%1, %2, %3, %4};"
                 :: "l"(p), "f"(a), "f"(b), "f"(c), "f"(d) : "memory");
}

// ---------------------------------------------------------------------------
// Prep kernels
// ---------------------------------------------------------------------------
__global__ void zero_kernel(int N) {
    int i = blockIdx.x * blockDim.x + threadIdx.x;
    int stride = gridDim.x * blockDim.x;
    if (i == 0) g_is32 = 0;
    int n4 = N * 16;
    float4 z = make_float4(0.f, 0.f, 0.f, 0.f);
    for (int j = i; j < n4; j += stride) ((float4*)g_agg)[j] = z;
    for (int j = i; j < N; j += stride) g_cnt[j] = 0.f;
}

// Dtype probe: int64 data -> first E words all in [0,N); int32 data -> packed
// pairs, some word >= 2^32 -> flag.
__global__ void detect_kernel(const long long* __restrict__ ei64, int E, int N) {
    int i = blockIdx.x * blockDim.x + threadIdx.x;
    int stride = gridDim.x * blockDim.x;
    int bad = 0;
    for (int j = i; j < E; j += stride) {
        long long v = ei64[j];
        if (v < 0 || v >= (long long)N) bad = 1;
    }
    if (__ballot_sync(0xffffffffu, bad) && (threadIdx.x & 31) == 0)
        atomicOr(&g_is32, 1);
}

__global__ void convert_kernel(const void* __restrict__ eiraw, int E, int N) {
    int i = blockIdx.x * blockDim.x + threadIdx.x;
    int stride = gridDim.x * blockDim.x;
    int is32 = g_is32;
    if (is32) {
        const int* p = (const int*)eiraw;
        for (int j = i; j < E; j += stride) {
            g_row[j] = min(max(p[j], 0), N - 1);
            g_col[j] = min(max(p[E + j], 0), N - 1);
        }
    } else {
        const long long* p = (const long long*)eiraw;
        for (int j = i; j < E; j += stride) {
            g_row[j] = min(max((int)p[j], 0), N - 1);
            g_col[j] = min(max((int)p[E + j], 0), N - 1);
        }
    }
}

// ---------------------------------------------------------------------------
// Shared tile machinery: M-tile=64 rows, 512 threads = 16 warps (4 rt x 4 nh).
// A buffer [64][136] fp32 (tf32-rounded values), in-place layer ping-pong.
// Weights W[k][n] row-major in SMEM (ldm 136 / 72). Bias as 16-row broadcast
// tiles for accumulator init.
// ---------------------------------------------------------------------------
#define LDA 136

// One MLP layer: acc = BT ++ A(rt rows) @ W, then elementwise f, store to A.
// NTW = n-tiles (of 16) per nh group. KS = K/8 steps.
template <int KS, int NTW, bool TF32OUT>
__device__ __forceinline__ void mlp_layer(const float* __restrict__ Ab,
                                          const float* __restrict__ W, int ldw,
                                          const float* __restrict__ BT, int ldbt,
                                          float* __restrict__ Ao,
                                          int rt, int nh) {
    wmma::fragment<wmma::accumulator, 16, 16, 8, float> acc[NTW];
#pragma unroll
    for (int nt = 0; nt < NTW; nt++)
        wmma::load_matrix_sync(acc[nt], BT + (nh * NTW + nt) * 16, ldbt,
                               wmma::mem_row_major);
#pragma unroll 2
    for (int ks = 0; ks < KS; ks++) {
        wmma::fragment<wmma::matrix_a, 16, 16, 8, wmma::precision::tf32,
                       wmma::row_major> af;
        wmma::load_matrix_sync(af, Ab + rt * 16 * LDA + ks * 8, LDA);
#pragma unroll
        for (int nt = 0; nt < NTW; nt++) {
            wmma::fragment<wmma::matrix_b, 16, 16, 8, wmma::precision::tf32,
                           wmma::row_major> bf;
            wmma::load_matrix_sync(bf, W + ks * 8 * ldw + (nh * NTW + nt) * 16, ldw);
            wmma::mma_sync(acc[nt], af, bf, acc[nt]);
        }
    }
    __syncthreads();  // all reads of A done before overwrite
#pragma unroll
    for (int nt = 0; nt < NTW; nt++) {
#pragma unroll
        for (int i = 0; i < acc[nt].num_elements; i++) {
            float v = lrelu(acc[nt].x[i]);
            acc[nt].x[i] = TF32OUT ? to_tf32(v) : v;
        }
        wmma::store_matrix_sync(Ao + rt * 16 * LDA + (nh * NTW + nt) * 16,
                                acc[nt], LDA, wmma::mem_row_major);
    }
    __syncthreads();
}

// ---------------------------------------------------------------------------
// Edge kernel. SMEM bytes:
// A 34816 | W0 52224 | W1 69632 | W2 36864 | BT0 8192 | BT1 8192 | BT2 4096 | LN 512
#define E_A 0
#define E_W0 34816
#define E_W1 87040
#define E_W2 156672
#define E_BT0 193536
#define E_BT1 201728
#define E_BT2 209920
#define E_LN 214016
#define E_SM 214528

__global__ __launch_bounds__(512, 1)
void edge_tc(const float* __restrict__ x, const float* __restrict__ ea,
             const float* __restrict__ w0g, const float* __restrict__ b0g,
             const float* __restrict__ w1g, const float* __restrict__ b1g,
             const float* __restrict__ w2g, const float* __restrict__ b2g,
             const float* __restrict__ gg, const float* __restrict__ btg, int E) {
    extern __shared__ char sm[];
    float* A = (float*)(sm + E_A);
    float* W0 = (float*)(sm + E_W0);
    float* W1 = (float*)(sm + E_W1);
    float* W2 = (float*)(sm + E_W2);
    float* BT0 = (float*)(sm + E_BT0);
    float* BT1 = (float*)(sm + E_BT1);
    float* BT2 = (float*)(sm + E_BT2);
    float* LN = (float*)(sm + E_LN);  // [0:64) gamma, [64:128) beta

    int tid = threadIdx.x;
    for (int i = tid; i < 96 * 128; i += 512) {
        int k = i >> 7, n = i & 127;
        W0[k * LDA + n] = to_tf32(w0g[i]);
    }
    for (int i = tid; i < 128 * 128; i += 512) {
        int k = i >> 7, n = i & 127;
        W1[k * LDA + n] = to_tf32(w1g[i]);
    }
    for (int i = tid; i < 128 * 64; i += 512) {
        int k = i >> 6, n = i & 63;
        W2[k * 72 + n] = to_tf32(w2g[i]);
    }
    for (int i = tid; i < 16 * 128; i += 512) {
        int n = i & 127;
        BT0[i] = b0g[n];
        BT1[i] = b1g[n];
    }
    for (int i = tid; i < 16 * 64; i += 512) BT2[i] = b2g[i & 63];
    if (tid < 64) { LN[tid] = gg[tid]; LN[64 + tid] = btg[tid]; }
    __syncthreads();

    int warp = tid >> 5;
    int rt = warp & 3, nh = warp >> 2;
    int r = tid >> 3, seg = tid & 7;  // gather/LN role: 8 threads per row
    int ntiles = (E + 63) >> 6;

    for (int gi = blockIdx.x; gi < ntiles; gi += gridDim.x) {
        int e = (gi << 6) + r;
        bool ok = e < E;
        // ---- Gather: row r, 96 cols (x[row] 64 ++ ea 32), 3 float4 per thread
        {
            int rw = ok ? g_row[e] : 0;
            const float4* xp = (const float4*)(x + (size_t)rw * 64);
            const float4* ep = (const float4*)(ea + (size_t)e * 32);
#pragma unroll
            for (int j = 0; j < 3; j++) {
                int q = seg * 3 + j;
                float4 v = ok ? (q < 16 ? __ldg(xp + q) : __ldg(ep + (q - 16)))
                              : make_float4(0.f, 0.f, 0.f, 0.f);
                float4 o = make_float4(to_tf32(v.x), to_tf32(v.y),
                                       to_tf32(v.z), to_tf32(v.w));
                *(float4*)(A + r * LDA + q * 4) = o;
            }
        }
        __syncthreads();
        // ---- 3 layers
        mlp_layer<12, 2, true>(A, W0, LDA, BT0, 128, A, rt, nh);
        mlp_layer<16, 2, true>(A, W1, LDA, BT1, 128, A, rt, nh);
        mlp_layer<16, 1, false>(A, W2, 72, BT2, 64, A, rt, nh);
        // ---- LayerNorm per row + atomic scatter (A holds 64x64 post-lrelu)
        {
            float4 v0 = *(float4*)(A + r * LDA + seg * 8);
            float4 v1 = *(float4*)(A + r * LDA + seg * 8 + 4);
            float s = v0.x + v0.y + v0.z + v0.w + v1.x + v1.y + v1.z + v1.w;
#pragma unroll
            for (int off = 4; off; off >>= 1) s += __shfl_xor_sync(0xffffffffu, s, off);
            float mu = s * (1.f / 64.f);
            float d[8] = {v0.x - mu, v0.y - mu, v0.z - mu, v0.w - mu,
                          v1.x - mu, v1.y - mu, v1.z - mu, v1.w - mu};
            float q = 0.f;
#pragma unroll
            for (int j = 0; j < 8; j++) q += d[j] * d[j];
#pragma unroll
            for (int off = 4; off; off >>= 1) q += __shfl_xor_sync(0xffffffffu, q, off);
            float rs = rsqrtf(q * (1.f / 64.f) + 1e-5f);
            if (ok) {
                int c = g_col[e];
                float* dst = g_agg + (size_t)c * 64 + seg * 8;
                int b = seg * 8;
                red_add_v4(dst,
                           d[0] * rs * LN[b + 0] + LN[64 + b + 0],
                           d[1] * rs * LN[b + 1] + LN[64 + b + 1],
                           d[2] * rs * LN[b + 2] + LN[64 + b + 2],
                           d[3] * rs * LN[b + 3] + LN[64 + b + 3]);
                red_add_v4(dst + 4,
                           d[4] * rs * LN[b + 4] + LN[64 + b + 4],
                           d[5] * rs * LN[b + 5] + LN[64 + b + 5],
                           d[6] * rs * LN[b + 6] + LN[64 + b + 6],
                           d[7] * rs * LN[b + 7] + LN[64 + b + 7]);
                if (seg == 0) atomicAdd(g_cnt + c, 1.f);
            }
        }
        __syncthreads();
    }
}

// ---------------------------------------------------------------------------
// Node kernel. SMEM bytes:
// A 34816 | W0 69632 | W1 69632 | W2 36864 | BT0 8192 | BT1 8192 | BT2 4096 | LN 512
#define M_A 0
#define M_W0 34816
#define M_W1 104448
#define M_W2 174080
#define M_BT0 210944
#define M_BT1 219136
#define M_BT2 227328
#define M_LN 231424
#define M_SM 231936

__global__ __launch_bounds__(512, 1)
void node_tc(const float* __restrict__ x,
             const float* __restrict__ w0g, const float* __restrict__ b0g,
             const float* __restrict__ w1g, const float* __restrict__ b1g,
             const float* __restrict__ w2g, const float* __restrict__ b2g,
             const float* __restrict__ gg, const float* __restrict__ btg,
             float* __restrict__ out, int N) {
    extern __shared__ char sm[];
    float* A = (float*)(sm + M_A);
    float* W0 = (float*)(sm + M_W0);
    float* W1 = (float*)(sm + M_W1);
    float* W2 = (float*)(sm + M_W2);
    float* BT0 = (float*)(sm + M_BT0);
    float* BT1 = (float*)(sm + M_BT1);
    float* BT2 = (float*)(sm + M_BT2);
    float* LN = (float*)(sm + M_LN);

    int tid = threadIdx.x;
    for (int i = tid; i < 128 * 128; i += 512) {
        int k = i >> 7, n = i & 127;
        W0[k * LDA + n] = to_tf32(w0g[i]);
        W1[k * LDA + n] = to_tf32(w1g[i]);
    }
    for (int i = tid; i < 128 * 64; i += 512) {
        int k = i >> 6, n = i & 63;
        W2[k * 72 + n] = to_tf32(w2g[i]);
    }
    for (int i = tid; i < 16 * 128; i += 512) {
        int n = i & 127;
        BT0[i] = b0g[n];
        BT1[i] = b1g[n];
    }
    for (int i = tid; i < 16 * 64; i += 512) BT2[i] = b2g[i & 63];
    if (tid < 64) { LN[tid] = gg[tid]; LN[64 + tid] = btg[tid]; }
    __syncthreads();

    int warp = tid >> 5;
    int rt = warp & 3, nh = warp >> 2;
    int r = tid >> 3, seg = tid & 7;
    int ntiles = (N + 63) >> 6;

    for (int gi = blockIdx.x; gi < ntiles; gi += gridDim.x) {
        int n = (gi << 6) + r;
        bool ok = n < N;
        // ---- Gather: 128 cols (x 64 ++ agg/max(cnt,1) 64), 4 float4/thread
        {
            float inv = ok ? 1.f / fmaxf(g_cnt[n], 1.f) : 0.f;
            const float4* xp = (const float4*)(x + (size_t)n * 64);
            const float4* ap = (const float4*)(g_agg + (size_t)n * 64);
#pragma unroll
            for (int j = 0; j < 4; j++) {
                int q = seg * 4 + j;
                float4 v, o;
                if (q < 16) {
                    v = ok ? __ldg(xp + q) : make_float4(0.f, 0.f, 0.f, 0.f);
                    o = make_float4(to_tf32(v.x), to_tf32(v.y), to_tf32(v.z), to_tf32(v.w));
                } else {
                    v = ok ? ap[q - 16] : make_float4(0.f, 0.f, 0.f, 0.f);
                    o = make_float4(to_tf32(v.x * inv), to_tf32(v.y * inv),
                                    to_tf32(v.z * inv), to_tf32(v.w * inv));
                }
                *(float4*)(A + r * LDA + q * 4) = o;
            }
        }
        __syncthreads();
        mlp_layer<16, 2, true>(A, W0, LDA, BT0, 128, A, rt, nh);
        mlp_layer<16, 2, true>(A, W1, LDA, BT1, 128, A, rt, nh);
        mlp_layer<16, 1, false>(A, W2, 72, BT2, 64, A, rt, nh);
        // ---- LayerNorm per row + store
        {
            float4 v0 = *(float4*)(A + r * LDA + seg * 8);
            float4 v1 = *(float4*)(A + r * LDA + seg * 8 + 4);
            float s = v0.x + v0.y + v0.z + v0.w + v1.x + v1.y + v1.z + v1.w;
#pragma unroll
            for (int off = 4; off; off >>= 1) s += __shfl_xor_sync(0xffffffffu, s, off);
            float mu = s * (1.f / 64.f);
            float d[8] = {v0.x - mu, v0.y - mu, v0.z - mu, v0.w - mu,
                          v1.x - mu, v1.y - mu, v1.z - mu, v1.w - mu};
            float q = 0.f;
#pragma unroll
            for (int j = 0; j < 8; j++) q += d[j] * d[j];
#pragma unroll
            for (int off = 4; off; off >>= 1) q += __shfl_xor_sync(0xffffffffu, q, off);
            float rs = rsqrtf(q * (1.f / 64.f) + 1e-5f);
            if (ok) {
                int b = seg * 8;
                float4 o0 = make_float4(d[0] * rs * LN[b + 0] + LN[64 + b + 0],
                                        d[1] * rs * LN[b + 1] + LN[64 + b + 1],
                                        d[2] * rs * LN[b + 2] + LN[64 + b + 2],
                                        d[3] * rs * LN[b + 3] + LN[64 + b + 3]);
                float4 o1 = make_float4(d[4] * rs * LN[b + 4] + LN[64 + b + 4],
                                        d[5] * rs * LN[b + 5] + LN[64 + b + 5],
                                        d[6] * rs * LN[b + 6] + LN[64 + b + 6],
                                        d[7] * rs * LN[b + 7] + LN[64 + b + 7]);
                float4* op = (float4*)(out + (size_t)n * 64 + b);
                op[0] = o0;
                op[1] = o1;
            }
        }
        __syncthreads();
    }
}

// ---------------------------------------------------------------------------
extern "C" void kernel_launch(void* const* d_in, const int* in_sizes, int n_in,
                              void* d_out, int out_size) {
    const float* x = (const float*)d_in[0];
    const void* ei = (const void*)d_in[1];
    const float* ea = (const float*)d_in[2];
    const float* m1w0 = (const float*)d_in[5];
    const float* m1b0 = (const float*)d_in[6];
    const float* m1w1 = (const float*)d_in[7];
    const float* m1b1 = (const float*)d_in[8];
    const float* m1w2 = (const float*)d_in[9];
    const float* m1b2 = (const float*)d_in[10];
    const float* ln1g = (const float*)d_in[11];
    const float* ln1b = (const float*)d_in[12];
    const float* m2w0 = (const float*)d_in[13];
    const float* m2b0 = (const float*)d_in[14];
    const float* m2w1 = (const float*)d_in[15];
    const float* m2b1 = (const float*)d_in[16];
    const float* m2w2 = (const float*)d_in[17];
    const float* m2b2 = (const float*)d_in[18];
    const float* ln2g = (const float*)d_in[19];
    const float* ln2b = (const float*)d_in[20];

    int N = in_sizes[0] / 64;
    int E = in_sizes[1] / 2;
    if (N > N_MAX) N = N_MAX;
    if (E > E_MAX) E = E_MAX;
    float* out = (float*)d_out;

    int dev = 0;
    cudaGetDevice(&dev);
    int nsm = 148;
    cudaDeviceGetAttribute(&nsm, cudaDevAttrMultiProcessorCount, dev);

    zero_kernel<<<256, 256>>>(N);
    detect_kernel<<<512, 256>>>((const long long*)ei, E, N);
    convert_kernel<<<512, 256>>>(ei, E, N);

    cudaFuncSetAttribute(edge_tc, cudaFuncAttributeMaxDynamicSharedMemorySize, E_SM);
    cudaFuncSetAttribute(node_tc, cudaFuncAttributeMaxDynamicSharedMemorySize, M_SM);

    edge_tc<<<nsm, 512, E_SM>>>(x, ea, m1w0, m1b0, m1w1, m1b1, m1w2, m1b2,
                                ln1g, ln1b, E);
    node_tc<<<nsm, 512, M_SM>>>(x, m2w0, m2b0, m2w1, m2b1, m2w2, m2b2,
                                ln2g, ln2b, out, N);
}